// round 1
// baseline (speedup 1.0000x reference)
#include <cuda_runtime.h>
#include <math_constants.h>

#define BB   32
#define TT   2048
#define SINDIM 1024
#define HINDIM 1024
#define KDIM 512
#define VDIM 512
#define NBLK 16            // main-kernel blocks per batch
#define WPB  8             // warps per block
#define PW   (NBLK*WPB)    // t-stride (128)
#define KSPLIT 16

// ---- scratch (device globals; no allocations allowed) ----
__device__ float g_query[BB*KDIM];
__device__ float g_qhp[KSPLIT*BB*HINDIM];
__device__ float g_qh[BB*HINDIM];
__device__ float g_qb[BB];
__device__ float g_e[BB*TT];
__device__ float g_pm[BB*NBLK];
__device__ float g_pz[BB*NBLK];
__device__ float g_pacc[BB*NBLK*HINDIM];
__device__ float g_ctxh[BB*HINDIM];

__device__ __forceinline__ float warp_sum(float v) {
#pragma unroll
    for (int o = 16; o > 0; o >>= 1) v += __shfl_xor_sync(0xffffffffu, v, o);
    return v;
}

// query[b,k] = Ws[k,:]·dec[b,:] + bs[k].  One warp computes k for 4 batches.
__global__ void k_query(const float* __restrict__ dec, const float* __restrict__ Ws,
                        const float* __restrict__ bs) {
    int gw   = blockIdx.x * WPB + (threadIdx.x >> 5);
    int lane = threadIdx.x & 31;
    int k  = gw % KDIM;
    int b0 = (gw / KDIM) * 4;
    const float4* w4 = (const float4*)(Ws + (size_t)k * SINDIM);
    float4 w[8];
#pragma unroll
    for (int j = 0; j < 8; j++) w[j] = w4[lane + 32*j];
    float bias = bs[k];
#pragma unroll
    for (int bb = 0; bb < 4; bb++) {
        const float4* s4 = (const float4*)(dec + (size_t)(b0+bb) * SINDIM);
        float a = 0.f;
#pragma unroll
        for (int j = 0; j < 8; j++) {
            float4 s = s4[lane + 32*j];
            a += w[j].x*s.x + w[j].y*s.y + w[j].z*s.z + w[j].w*s.w;
        }
        a = warp_sum(a);
        if (lane == 0) g_query[(b0+bb)*KDIM + k] = a + bias;
    }
}

// qb[b] = query[b,:]·bh
__global__ void k_qb(const float* __restrict__ bh) {
    int b = threadIdx.x >> 5, lane = threadIdx.x & 31;
    float a = 0.f;
    for (int j = lane; j < KDIM; j += 32) a += g_query[b*KDIM + j] * bh[j];
    a = warp_sum(a);
    if (lane == 0) g_qb[b] = a;
}

// qh partials: qh[b,h] = sum_k Wh[k,h]*query[b,k], k-split for parallelism.
__global__ void k_qhp(const float* __restrict__ Wh) {
    __shared__ float sq[BB * (KDIM / KSPLIT)];
    const int KCH = KDIM / KSPLIT;  // 32
    int tid = threadIdx.x;
    int h   = blockIdx.x * 256 + tid;
    int k0  = blockIdx.y * KCH;
    for (int i = tid; i < BB*KCH; i += 256) {
        int b = i / KCH, kk = i % KCH;
        sq[i] = g_query[b*KDIM + k0 + kk];
    }
    __syncthreads();
    float acc[BB];
#pragma unroll
    for (int b = 0; b < BB; b++) acc[b] = 0.f;
    for (int kk = 0; kk < KCH; kk++) {
        float wh = Wh[(size_t)(k0+kk) * HINDIM + h];
#pragma unroll
        for (int b = 0; b < BB; b++) acc[b] += wh * sq[b*KCH + kk];
    }
    for (int b = 0; b < BB; b++)
        g_qhp[((size_t)blockIdx.y*BB + b)*HINDIM + h] = acc[b];
}

__global__ void k_qhmerge() {
    int i = blockIdx.x * 256 + threadIdx.x;
    float s = 0.f;
#pragma unroll
    for (int j = 0; j < KSPLIT; j++) s += g_qhp[(size_t)j*BB*HINDIM + i];
    g_qh[i] = s;
}

// MAIN: single streaming pass over listener_output with online masked softmax.
// grid (NBLK, BB), 256 threads. Warp ws handles t = ws, ws+PW, ... (< len[b]).
__global__ void __launch_bounds__(256) k_main(const float* __restrict__ lo,
                                              const int* __restrict__ lens) {
    __shared__ float s_m[WPB], s_zs[WPB];
    __shared__ float s_acc[WPB][HINDIM];
    const int b      = blockIdx.y;
    const int warpId = threadIdx.x >> 5;
    const int lane   = threadIdx.x & 31;
    const int ws     = blockIdx.x * WPB + warpId;
    const int len    = (b == 0) ? TT : lens[b];   // ref never masks sample 0

    const float4* qh4 = (const float4*)(g_qh + (size_t)b * HINDIM);
    float4 q[8];
#pragma unroll
    for (int j = 0; j < 8; j++) q[j] = qh4[lane + 32*j];
    const float qb = g_qb[b];

    float4 acc[8];
#pragma unroll
    for (int j = 0; j < 8; j++) acc[j] = make_float4(0.f, 0.f, 0.f, 0.f);
    float m = -CUDART_INF_F, Z = 0.f;

    const float4* lob = (const float4*)(lo + (size_t)b * TT * HINDIM);
    for (int t = ws; t < len; t += PW) {
        const float4* h4 = lob + (size_t)t * (HINDIM/4);
        float4 hv[8];
#pragma unroll
        for (int j = 0; j < 8; j++) hv[j] = h4[lane + 32*j];
        float e = 0.f;
#pragma unroll
        for (int j = 0; j < 8; j++)
            e += hv[j].x*q[j].x + hv[j].y*q[j].y + hv[j].z*q[j].z + hv[j].w*q[j].w;
        e = warp_sum(e) + qb;                 // warp-uniform
        if (lane == 0) g_e[b*TT + t] = e;
        if (e > m) {                          // uniform branch
            float f = (m > -CUDART_INF_F) ? __expf(m - e) : 0.f;
            Z = Z * f + 1.f;
#pragma unroll
            for (int j = 0; j < 8; j++) {
                acc[j].x = acc[j].x * f + hv[j].x;
                acc[j].y = acc[j].y * f + hv[j].y;
                acc[j].z = acc[j].z * f + hv[j].z;
                acc[j].w = acc[j].w * f + hv[j].w;
            }
            m = e;
        } else {
            float w = __expf(e - m);
            Z += w;
#pragma unroll
            for (int j = 0; j < 8; j++) {
                acc[j].x += w * hv[j].x;
                acc[j].y += w * hv[j].y;
                acc[j].z += w * hv[j].z;
                acc[j].w += w * hv[j].w;
            }
        }
    }

    // in-block merge of 8 warp partials
    if (lane == 0) s_m[warpId] = m;
    __syncthreads();
    float mb = s_m[0];
#pragma unroll
    for (int w = 1; w < WPB; w++) mb = fmaxf(mb, s_m[w]);
    float f = (m > -CUDART_INF_F) ? __expf(m - mb) : 0.f;
    if (lane == 0) s_zs[warpId] = Z * f;
    float4* sa = (float4*)(&s_acc[warpId][0]);
#pragma unroll
    for (int j = 0; j < 8; j++) {
        float4 v = acc[j];
        v.x *= f; v.y *= f; v.z *= f; v.w *= f;
        sa[lane + 32*j] = v;
    }
    __syncthreads();
    int pid = b * NBLK + blockIdx.x;
    for (int h = threadIdx.x; h < HINDIM; h += 256) {
        float s = 0.f;
#pragma unroll
        for (int w = 0; w < WPB; w++) s += s_acc[w][h];
        g_pacc[(size_t)pid * HINDIM + h] = s;
    }
    if (threadIdx.x == 0) {
        float zb = 0.f;
#pragma unroll
        for (int w = 0; w < WPB; w++) zb += s_zs[w];
        g_pm[pid] = mb; g_pz[pid] = zb;
    }
}

// cross-block LSE merge per batch; emits attn and ctxh (= Σ attn·h / Z).
__global__ void k_bmerge(const int* __restrict__ lens, float* __restrict__ out) {
    __shared__ float sf[NBLK];
    __shared__ float red[256];
    const int b = blockIdx.x, tid = threadIdx.x;
    float m = -CUDART_INF_F;
    if (tid < NBLK) m = g_pm[b*NBLK + tid];
    red[tid] = m; __syncthreads();
#pragma unroll
    for (int s = 128; s > 0; s >>= 1) {
        if (tid < s) red[tid] = fmaxf(red[tid], red[tid+s]);
        __syncthreads();
    }
    m = red[0];
    __syncthreads();
    float zc = 0.f;
    if (tid < NBLK) {
        float pm = g_pm[b*NBLK + tid];
        float fj = (pm > -CUDART_INF_F) ? __expf(pm - m) : 0.f;
        sf[tid] = fj;
        zc = g_pz[b*NBLK + tid] * fj;
    }
    red[tid] = zc; __syncthreads();
#pragma unroll
    for (int s = 128; s > 0; s >>= 1) {
        if (tid < s) red[tid] += red[tid+s];
        __syncthreads();
    }
    float invZ = 1.f / fmaxf(red[0], 1e-12f);

    for (int h = tid; h < HINDIM; h += 256) {
        float s = 0.f;
#pragma unroll
        for (int j = 0; j < NBLK; j++)
            s += g_pacc[(size_t)(b*NBLK + j)*HINDIM + h] * sf[j];
        g_ctxh[b*HINDIM + h] = s * invZ;
    }
    const int len = (b == 0) ? TT : lens[b];
    float* oat = out + BB*VDIM + (size_t)b*TT;
    for (int t = tid; t < TT; t += 256)
        oat[t] = (t < len) ? __expf(g_e[b*TT + t] - m) * invZ : 0.f;
}

// context[b,v] = Wv[v,:]·ctxh[b,:] + bv[v]   (Σattn = 1 after renorm)
__global__ void k_context(const float* __restrict__ Wv, const float* __restrict__ bv,
                          float* __restrict__ out) {
    int gw   = blockIdx.x * WPB + (threadIdx.x >> 5);
    int lane = threadIdx.x & 31;
    int v  = gw % VDIM;
    int b0 = (gw / VDIM) * 4;
    const float4* w4 = (const float4*)(Wv + (size_t)v * HINDIM);
    float4 w[8];
#pragma unroll
    for (int j = 0; j < 8; j++) w[j] = w4[lane + 32*j];
    float bias = bv[v];
#pragma unroll
    for (int bb = 0; bb < 4; bb++) {
        const float4* c4 = (const float4*)(g_ctxh + (size_t)(b0+bb) * HINDIM);
        float a = 0.f;
#pragma unroll
        for (int j = 0; j < 8; j++) {
            float4 c = c4[lane + 32*j];
            a += w[j].x*c.x + w[j].y*c.y + w[j].z*c.z + w[j].w*c.w;
        }
        a = warp_sum(a);
        if (lane == 0) out[(b0+bb)*VDIM + v] = a + bias;
    }
}

extern "C" void kernel_launch(void* const* d_in, const int* in_sizes, int n_in,
                              void* d_out, int out_size) {
    const float* dec = (const float*)d_in[0];
    const float* lo  = (const float*)d_in[1];
    const int*   len = (const int*)  d_in[2];
    const float* Ws  = (const float*)d_in[3];
    const float* bs  = (const float*)d_in[4];
    const float* Wh  = (const float*)d_in[5];
    const float* bh  = (const float*)d_in[6];
    const float* Wv  = (const float*)d_in[7];
    const float* bv  = (const float*)d_in[8];
    float* out = (float*)d_out;

    k_query  <<<KDIM * (BB/4) / WPB, 256>>>(dec, Ws, bs);   // 512 blocks
    k_qb     <<<1, BB*32>>>(bh);
    k_qhp    <<<dim3(HINDIM/256, KSPLIT), 256>>>(Wh);
    k_qhmerge<<<BB*HINDIM/256, 256>>>();
    k_main   <<<dim3(NBLK, BB), 256>>>(lo, len);
    k_bmerge <<<BB, 256>>>(len, out);
    k_context<<<VDIM * (BB/4) / WPB, 256>>>(Wv, bv, out);
}